// round 1
// baseline (speedup 1.0000x reference)
#include <cuda_runtime.h>

// Problem: PolylineEncoder
//   polylines      [32,512,64,9]  f32
//   polylines_mask [32,512,64]    (assumed int32, nonzero = valid)
//   W1 [9,128], b1 [128], W2 [128,128], b2 [128]  f32
//   out [32,512,128] f32
//
// per polyline: h = relu(x @ W1 + b1); feat = h @ W2 + b2;
//   feat[invalid] = -1e9; pooled = max over n; all-invalid -> 0.

#define NPTS 64
#define CIN 9
#define HID 128
#define POLYS_PER_CTA 8
#define HT_STRIDE 68          // 64 + 4 pad: keeps 16B alignment, breaks bank conflicts
#define NEG_INF_F (-1e9f)

#define SMEM_W2   0                               // 128*128 floats   = 65536 B
#define SMEM_HT   (HID * HID)                     // 128*68 floats    = 34816 B
#define SMEM_XS   (SMEM_HT + HID * HT_STRIDE)     // 64*9 floats      = 2304 B
#define SMEM_MSK  (SMEM_XS + NPTS * CIN)          // 64 ints          = 256 B
#define SMEM_FLOATS (SMEM_MSK + NPTS)
#define SMEM_BYTES  (SMEM_FLOATS * 4)             // 102912 B

extern __shared__ float smem[];

__global__ void __launch_bounds__(128)
polyline_encoder_kernel(const float* __restrict__ poly,
                        const int*   __restrict__ mask,
                        const float* __restrict__ W1,
                        const float* __restrict__ b1,
                        const float* __restrict__ W2,
                        const float* __restrict__ b2,
                        float* __restrict__ out)
{
    float* W2s = smem + SMEM_W2;
    float* hT  = smem + SMEM_HT;
    float* xs  = smem + SMEM_XS;
    int*   msk = (int*)(smem + SMEM_MSK);

    const int tid = threadIdx.x;

    // ---- stage W2 into smem once per CTA (coalesced float4) ----
    {
        const float4* g = (const float4*)W2;
        float4* s = (float4*)W2s;
        #pragma unroll
        for (int i = 0; i < 32; ++i)            // 32 * 128 = 4096 float4 = 64 KB
            s[i * 128 + tid] = g[i * 128 + tid];
    }

    // ---- per-thread layer-1 weights: thread tid computes hidden channel hh = tid ----
    float w1r[CIN];
    #pragma unroll
    for (int c = 0; c < CIN; ++c) w1r[c] = W1[c * HID + tid];
    const float b1r = b1[tid];

    // ---- thread tile mapping for the 64x128 GEMM: 8n x 8d per thread ----
    const int dt = tid >> 3;    // 0..15  -> d0 = dt*8
    const int nt = tid & 7;     // 0..7   -> n0 = nt*8

    float b2r[8];
    #pragma unroll
    for (int j = 0; j < 8; ++j) b2r[j] = b2[dt * 8 + j];

    for (int pp = 0; pp < POLYS_PER_CTA; ++pp) {
        const int bp = blockIdx.x * POLYS_PER_CTA + pp;

        // barrier: previous iteration's GEMM reads of hT / epilogue reads of msk done
        __syncthreads();

        // ---- stage this polyline's points + mask ----
        const float* xg = poly + (size_t)bp * (NPTS * CIN);
        for (int i = tid; i < NPTS * CIN; i += 128) xs[i] = xg[i];
        int mv = 0;
        if (tid < NPTS) { mv = mask[(size_t)bp * NPTS + tid]; msk[tid] = mv; }
        const int anyv = __syncthreads_or(mv != 0);   // also fences xs/msk stores

        // ---- layer 1: hT[hh][n] = relu(b1 + x[n,:] . W1[:,hh]), hh = tid ----
        #pragma unroll 4
        for (int n = 0; n < NPTS; ++n) {
            float a = b1r;
            #pragma unroll
            for (int c = 0; c < CIN; ++c) a = fmaf(xs[n * CIN + c], w1r[c], a);
            hT[tid * HT_STRIDE + n] = fmaxf(a, 0.0f);
        }
        __syncthreads();

        // ---- GEMM: feat[n][d] = sum_hh hT[hh][n] * W2[hh][d] ----
        float acc[8][8];
        #pragma unroll
        for (int i = 0; i < 8; ++i)
            #pragma unroll
            for (int j = 0; j < 8; ++j) acc[i][j] = 0.0f;

        const float4* hbase = ((const float4*)hT)  + nt * 2;  // row stride 17 float4
        const float4* wbase = ((const float4*)W2s) + dt * 2;  // row stride 32 float4

        #pragma unroll 2
        for (int hh = 0; hh < HID; ++hh) {
            const float4 ha = hbase[hh * (HT_STRIDE / 4)];
            const float4 hb = hbase[hh * (HT_STRIDE / 4) + 1];
            const float4 wa = wbase[hh * (HID / 4)];
            const float4 wb = wbase[hh * (HID / 4) + 1];
            const float hv[8] = {ha.x, ha.y, ha.z, ha.w, hb.x, hb.y, hb.z, hb.w};
            const float wv[8] = {wa.x, wa.y, wa.z, wa.w, wb.x, wb.y, wb.z, wb.w};
            #pragma unroll
            for (int i = 0; i < 8; ++i)
                #pragma unroll
                for (int j = 0; j < 8; ++j)
                    acc[i][j] = fmaf(hv[i], wv[j], acc[i][j]);
        }

        // ---- masked max over this thread's 8 points ----
        float mx[8];
        #pragma unroll
        for (int j = 0; j < 8; ++j) mx[j] = NEG_INF_F;
        #pragma unroll
        for (int i = 0; i < 8; ++i) {
            if (msk[nt * 8 + i] != 0) {
                #pragma unroll
                for (int j = 0; j < 8; ++j) mx[j] = fmaxf(mx[j], acc[i][j]);
            }
        }

        // ---- reduce across the 8 n-tiles (consecutive lanes nt=0..7) ----
        #pragma unroll
        for (int off = 1; off < 8; off <<= 1) {
            #pragma unroll
            for (int j = 0; j < 8; ++j) {
                const float o = __shfl_xor_sync(0xffffffffu, mx[j], off);
                mx[j] = fmaxf(mx[j], o);
            }
        }

        // ---- write: +b2 hoisted out of the max (constant over n) ----
        if (nt == 0) {
            float4 o0, o1;
            if (anyv) {
                o0 = make_float4(mx[0] + b2r[0], mx[1] + b2r[1],
                                 mx[2] + b2r[2], mx[3] + b2r[3]);
                o1 = make_float4(mx[4] + b2r[4], mx[5] + b2r[5],
                                 mx[6] + b2r[6], mx[7] + b2r[7]);
            } else {
                o0 = make_float4(0.f, 0.f, 0.f, 0.f);
                o1 = make_float4(0.f, 0.f, 0.f, 0.f);
            }
            float4* og = (float4*)(out + (size_t)bp * HID + dt * 8);
            og[0] = o0;
            og[1] = o1;
        }
    }
}

extern "C" void kernel_launch(void* const* d_in, const int* in_sizes, int n_in,
                              void* d_out, int out_size)
{
    const float* poly = (const float*)d_in[0];
    const int*   mask = (const int*)  d_in[1];
    const float* W1   = (const float*)d_in[2];
    const float* b1   = (const float*)d_in[3];
    const float* W2   = (const float*)d_in[4];
    const float* b2   = (const float*)d_in[5];
    float* out = (float*)d_out;

    const int n_poly = in_sizes[1] / NPTS;          // B*P = 16384
    const int grid = n_poly / POLYS_PER_CTA;        // 2048

    cudaFuncSetAttribute(polyline_encoder_kernel,
                         cudaFuncAttributeMaxDynamicSharedMemorySize, SMEM_BYTES);
    polyline_encoder_kernel<<<grid, 128, SMEM_BYTES>>>(poly, mask, W1, b1, W2, b2, out);
}

// round 2
// speedup vs baseline: 1.0918x; 1.0918x over previous
#include <cuda_runtime.h>

// PolylineEncoder:
//   polylines      [32,512,64,9]  f32
//   polylines_mask [32,512,64]    int32 (nonzero = valid)
//   W1 [9,128], b1 [128], W2 [128,128], b2 [128]  f32
//   out [32,512,128] f32
//
// per polyline: h = relu(x @ W1 + b1); feat = h @ W2 + b2;
//   feat[invalid] = -1e9; pooled = max over n; all-invalid -> 0.
//
// 256 threads = two independent 128-thread halves, each owning a stream of 8
// polylines; W2 staged once in smem and shared. 8 warps/SM (2 per SMSP) to
// cover LDS latency that limited the 128-thread version.

#define NPTS 64
#define CIN 9
#define HID 128
#define POLYS_PER_HALF 8
#define POLYS_PER_CTA 16
#define HT_STRIDE 68          // 64 + 4 pad: 16B-aligned rows, breaks bank conflicts
#define NEG_INF_F (-1e9f)

#define SMEM_W2   0                                   // 16384 floats = 64 KB
#define SMEM_HT   (HID * HID)                         // 2 x 128*68   = 69632 B
#define SMEM_XS   (SMEM_HT + 2 * HID * HT_STRIDE)     // 2 x 576
#define SMEM_MSK  (SMEM_XS + 2 * NPTS * CIN)          // 2 x 64 ints
#define SMEM_FLOATS (SMEM_MSK + 2 * NPTS)
#define SMEM_BYTES  (SMEM_FLOATS * 4)                 // 140288 B

extern __shared__ float smem[];

__global__ void __launch_bounds__(256)
polyline_encoder_kernel(const float* __restrict__ poly,
                        const int*   __restrict__ mask,
                        const float* __restrict__ W1,
                        const float* __restrict__ b1,
                        const float* __restrict__ W2,
                        const float* __restrict__ b2,
                        float* __restrict__ out)
{
    float* W2s = smem + SMEM_W2;

    const int tid  = threadIdx.x;
    const int half = tid >> 7;     // 0/1: which polyline stream
    const int ht   = tid & 127;    // thread id within the half

    float* hT  = smem + SMEM_HT  + half * (HID * HT_STRIDE);
    float* xs  = smem + SMEM_XS  + half * (NPTS * CIN);
    int*   msk = (int*)(smem + SMEM_MSK) + half * NPTS;

    // ---- stage W2 into smem once per CTA (coalesced float4, all 256 threads) ----
    {
        const float4* g = (const float4*)W2;
        float4* s = (float4*)W2s;
        #pragma unroll
        for (int i = 0; i < 16; ++i)            // 16 * 256 = 4096 float4 = 64 KB
            s[i * 256 + tid] = g[i * 256 + tid];
    }

    // ---- per-thread layer-1 weights: thread ht computes hidden channel hh = ht ----
    float w1r[CIN];
    #pragma unroll
    for (int c = 0; c < CIN; ++c) w1r[c] = W1[c * HID + ht];
    const float b1r = b1[ht];

    // ---- thread tile mapping for the 64x128 GEMM: 8n x 8d per thread ----
    const int dt = ht >> 3;    // 0..15  -> d0 = dt*8
    const int nt = ht & 7;     // 0..7   -> n0 = nt*8

    float b2r[8];
    #pragma unroll
    for (int j = 0; j < 8; ++j) b2r[j] = b2[dt * 8 + j];

    for (int pp = 0; pp < POLYS_PER_HALF; ++pp) {
        const int bp = blockIdx.x * POLYS_PER_CTA + half * POLYS_PER_HALF + pp;

        // previous iteration's GEMM/epilogue reads of hT and msk must be done
        __syncthreads();

        // ---- stage this polyline's points + mask ----
        const float* xg = poly + (size_t)bp * (NPTS * CIN);
        for (int i = ht; i < NPTS * CIN; i += 128) xs[i] = xg[i];
        if (ht < NPTS) msk[ht] = mask[(size_t)bp * NPTS + ht];
        __syncthreads();

        // ---- layer 1: hT[hh][n] = relu(b1 + x[n,:] . W1[:,hh]), hh = ht ----
        #pragma unroll 4
        for (int n = 0; n < NPTS; ++n) {
            float a = b1r;
            #pragma unroll
            for (int c = 0; c < CIN; ++c) a = fmaf(xs[n * CIN + c], w1r[c], a);
            hT[ht * HT_STRIDE + n] = fmaxf(a, 0.0f);
        }
        __syncthreads();

        // ---- GEMM: feat[n][d] = sum_hh hT[hh][n] * W2[hh][d] ----
        float acc[8][8];
        #pragma unroll
        for (int i = 0; i < 8; ++i)
            #pragma unroll
            for (int j = 0; j < 8; ++j) acc[i][j] = 0.0f;

        const float4* hbase = ((const float4*)hT)  + nt * 2;  // row stride 17 float4
        const float4* wbase = ((const float4*)W2s) + dt * 2;  // row stride 32 float4

        #pragma unroll 2
        for (int hh = 0; hh < HID; ++hh) {
            const float4 ha = hbase[hh * (HT_STRIDE / 4)];
            const float4 hb = hbase[hh * (HT_STRIDE / 4) + 1];
            const float4 wa = wbase[hh * (HID / 4)];
            const float4 wb = wbase[hh * (HID / 4) + 1];
            const float hv[8] = {ha.x, ha.y, ha.z, ha.w, hb.x, hb.y, hb.z, hb.w};
            const float wv[8] = {wa.x, wa.y, wa.z, wa.w, wb.x, wb.y, wb.z, wb.w};
            #pragma unroll
            for (int i = 0; i < 8; ++i)
                #pragma unroll
                for (int j = 0; j < 8; ++j)
                    acc[i][j] = fmaf(hv[i], wv[j], acc[i][j]);
        }

        // ---- masked max over this thread's 8 points + validity OR ----
        float mx[8];
        #pragma unroll
        for (int j = 0; j < 8; ++j) mx[j] = NEG_INF_F;
        int sv = 0;
        #pragma unroll
        for (int i = 0; i < 8; ++i) {
            const int m = msk[nt * 8 + i];
            sv |= m;
            if (m != 0) {
                #pragma unroll
                for (int j = 0; j < 8; ++j) mx[j] = fmaxf(mx[j], acc[i][j]);
            }
        }

        // ---- reduce across the 8 n-tiles (8 consecutive lanes nt=0..7) ----
        #pragma unroll
        for (int off = 1; off < 8; off <<= 1) {
            #pragma unroll
            for (int j = 0; j < 8; ++j) {
                const float o = __shfl_xor_sync(0xffffffffu, mx[j], off);
                mx[j] = fmaxf(mx[j], o);
            }
            sv |= __shfl_xor_sync(0xffffffffu, sv, off);
        }

        // ---- write: +b2 hoisted out of the max (constant over n) ----
        if (nt == 0) {
            float4 o0, o1;
            if (sv != 0) {
                o0 = make_float4(mx[0] + b2r[0], mx[1] + b2r[1],
                                 mx[2] + b2r[2], mx[3] + b2r[3]);
                o1 = make_float4(mx[4] + b2r[4], mx[5] + b2r[5],
                                 mx[6] + b2r[6], mx[7] + b2r[7]);
            } else {
                o0 = make_float4(0.f, 0.f, 0.f, 0.f);
                o1 = make_float4(0.f, 0.f, 0.f, 0.f);
            }
            float4* og = (float4*)(out + (size_t)bp * HID + dt * 8);
            og[0] = o0;
            og[1] = o1;
        }
    }
}

extern "C" void kernel_launch(void* const* d_in, const int* in_sizes, int n_in,
                              void* d_out, int out_size)
{
    const float* poly = (const float*)d_in[0];
    const int*   mask = (const int*)  d_in[1];
    const float* W1   = (const float*)d_in[2];
    const float* b1   = (const float*)d_in[3];
    const float* W2   = (const float*)d_in[4];
    const float* b2   = (const float*)d_in[5];
    float* out = (float*)d_out;

    const int n_poly = in_sizes[1] / NPTS;          // B*P = 16384
    const int grid = n_poly / POLYS_PER_CTA;        // 1024

    cudaFuncSetAttribute(polyline_encoder_kernel,
                         cudaFuncAttributeMaxDynamicSharedMemorySize, SMEM_BYTES);
    polyline_encoder_kernel<<<grid, 256, SMEM_BYTES>>>(poly, mask, W1, b1, W2, b2, out);
}